// round 1
// baseline (speedup 1.0000x reference)
#include <cuda_runtime.h>
#include <cuda_bf16.h>
#include <math.h>

// Problem constants
#define PB 4096     // batch
#define PF 2048     // features
#define PK 64       // concepts
#define PD 8        // box dim
#define PN 1024     // K*2D
#define KD 512      // K*D

// ---------------- scratch (__device__ globals: no runtime allocation) ----------------
__device__ float g_W[PF * PN];        // transposed weights W[f][n]
__device__ float g_theta[PB * PN];    // GEMM output
__device__ float g_ez[PB * KD];       // exp(+10 z)
__device__ float g_eZ[PB * KD];       // exp(-10 Z)
__device__ float g_inv[PB * KD];      // 1/softplus(2(Z-z))
__device__ float g_boxdot[PB];        // per-b flat_boxes @ Wbox partial

// ---------------- kernel 0: transpose Wp (K,F,2D) -> W[f][n], n = k*16+d ----------------
__global__ void transpose_wp(const float* __restrict__ Wp) {
    int idx = blockIdx.x * 256 + threadIdx.x;   // idx = f*1024 + n
    if (idx < PF * PN) {
        int f = idx >> 10;
        int n = idx & 1023;
        g_W[idx] = Wp[(n >> 4) * (PF * 16) + f * 16 + (n & 15)];
    }
}

// ---------------- kernel 1: SGEMM C[b][n] = sum_f A[b][f]*W[f][n] + bp[n] ----------------
// 128x128 tile, BK=16, 256 threads, 8x8 per thread, double-buffered smem.
__global__ __launch_bounds__(256) void sgemm_kernel(const float* __restrict__ A,
                                                    const float* __restrict__ bias) {
    __shared__ float As[2][16][132];
    __shared__ float Bs[2][16][132];

    const int tid = threadIdx.x;
    const int row0 = blockIdx.y * 128;   // m
    const int col0 = blockIdx.x * 128;   // n
    const int tx = tid & 15;
    const int ty = tid >> 4;
    const int m0 = ty * 8;
    const int n0 = tx * 8;

    // global->smem load indices
    const int ar = tid >> 2;           // 0..63 (A tile row, 2 rounds: +64)
    const int ac = (tid & 3) * 4;      // 0,4,8,12 (k within tile)
    const int br = tid >> 4;           // 0..15 (k row of B tile)
    const int bc = (tid & 15) * 4;     // 0..60 (n within tile, 2 rounds: +64)

    float acc[8][8];
#pragma unroll
    for (int i = 0; i < 8; i++)
#pragma unroll
        for (int j = 0; j < 8; j++) acc[i][j] = 0.f;

    auto loadTile = [&](int kt, int buf) {
        const float* Ap = A + (size_t)row0 * PF + kt * 16;
#pragma unroll
        for (int r = 0; r < 2; r++) {
            int arow = ar + r * 64;
            float4 v = *(const float4*)(Ap + (size_t)arow * PF + ac);
            As[buf][ac + 0][arow] = v.x;
            As[buf][ac + 1][arow] = v.y;
            As[buf][ac + 2][arow] = v.z;
            As[buf][ac + 3][arow] = v.w;
        }
        const float* Bp = g_W + (size_t)(kt * 16) * PN + col0;
#pragma unroll
        for (int r = 0; r < 2; r++) {
            float4 v = *(const float4*)(Bp + (size_t)br * PN + bc + r * 64);
            *(float4*)(&Bs[buf][br][bc + r * 64]) = v;
        }
    };

    loadTile(0, 0);
    __syncthreads();

    const int nk = PF / 16;
    for (int kt = 0; kt < nk; kt++) {
        int buf = kt & 1;
        if (kt + 1 < nk) loadTile(kt + 1, buf ^ 1);
#pragma unroll
        for (int kk = 0; kk < 16; kk++) {
            float a[8], b[8];
            float4 a0 = *(const float4*)(&As[buf][kk][m0]);
            float4 a1 = *(const float4*)(&As[buf][kk][m0 + 4]);
            float4 b0 = *(const float4*)(&Bs[buf][kk][n0]);
            float4 b1 = *(const float4*)(&Bs[buf][kk][n0 + 4]);
            a[0]=a0.x; a[1]=a0.y; a[2]=a0.z; a[3]=a0.w; a[4]=a1.x; a[5]=a1.y; a[6]=a1.z; a[7]=a1.w;
            b[0]=b0.x; b[1]=b0.y; b[2]=b0.z; b[3]=b0.w; b[4]=b1.x; b[5]=b1.y; b[6]=b1.z; b[7]=b1.w;
#pragma unroll
            for (int i = 0; i < 8; i++)
#pragma unroll
                for (int j = 0; j < 8; j++) acc[i][j] = fmaf(a[i], b[j], acc[i][j]);
        }
        __syncthreads();
    }

#pragma unroll
    for (int i = 0; i < 8; i++) {
        int m = row0 + m0 + i;
#pragma unroll
        for (int j = 0; j < 8; j += 4) {
            int n = col0 + n0 + j;
            float4 o;
            o.x = acc[i][j + 0] + bias[n + 0];
            o.y = acc[i][j + 1] + bias[n + 1];
            o.z = acc[i][j + 2] + bias[n + 2];
            o.w = acc[i][j + 3] + bias[n + 3];
            *(float4*)(g_theta + (size_t)m * PN + n) = o;
        }
    }
}

// accurate softplus
__device__ __forceinline__ float softplus_acc(float x) {
    float ax = fabsf(x);
    float r = log1pf(expf(-ax));
    return x > 0.f ? x + r : r;
}

// ---------------- kernel 2: per (b,k) prep ----------------
// z, Z, concept_probs, exp tables, invden, box-dot partial
__global__ void prep_kernel(const float* __restrict__ Wprob,
                            const float* __restrict__ bprob,
                            const float* __restrict__ Wbox,
                            float* __restrict__ out_cp) {
    const int b = blockIdx.x;
    const int k = threadIdx.x;   // 64 threads
    const float* th = g_theta + (size_t)b * PN + k * 16;

    float z[PD], Z[PD], v[PD];
#pragma unroll
    for (int d = 0; d < PD; d++) z[d] = th[d];
#pragma unroll
    for (int d = 0; d < PD; d++) {
        v[d] = softplus_acc(th[8 + d]);   // Z - z
        Z[d] = z[d] + v[d];
    }

    // concept logit
    const float* wp = Wprob + k * 16;
    float logit = bprob[k];
#pragma unroll
    for (int d = 0; d < PD; d++) logit += z[d] * wp[d] + Z[d] * wp[8 + d];
    float p = 1.f / (1.f + expf(-logit));
    out_cp[b * PK + k] = p;

    // box-dot partial: p * (z . Wbox[k][0:8] + Z . Wbox[k][8:16])
    const float* wb = Wbox + k * 16;
    float bd = 0.f;
#pragma unroll
    for (int d = 0; d < PD; d++) bd += z[d] * wb[d] + Z[d] * wb[8 + d];
    bd *= p;

    // exp tables + inverse box side
    const float C10 = 14.426950408889634f;  // 10/ln2
    float* ezp = g_ez + (size_t)b * KD + k * PD;
    float* eZp = g_eZ + (size_t)b * KD + k * PD;
    float* ivp = g_inv + (size_t)b * KD + k * PD;
#pragma unroll
    for (int d = 0; d < PD; d++) {
        ezp[d] = exp2f(z[d] * C10);
        eZp[d] = exp2f(-Z[d] * C10);
        float sp2 = 2.f * v[d] + log1pf(expf(-2.f * v[d]));  // softplus(2v), v>=0
        ivp[d] = 1.f / sp2;
    }

    // reduce bd over 64 threads (2 warps)
    __shared__ float red[64];
    red[k] = bd;
    __syncthreads();
    if (k < 32) {
        float s = red[k] + red[k + 32];
#pragma unroll
        for (int off = 16; off; off >>= 1) s += __shfl_down_sync(0xffffffffu, s, off);
        if (k == 0) g_boxdot[b] = s;
    }
}

// ---------------- kernel 3: pairwise cond + final task logit ----------------
__global__ __launch_bounds__(256) void pairwise_kernel(const float* __restrict__ Wrel,
                                                       const float* __restrict__ bbox,
                                                       const float* __restrict__ brel,
                                                       float* __restrict__ out_task,
                                                       float* __restrict__ out_cond) {
    const int b = blockIdx.x;
    const int tid = threadIdx.x;

    __shared__ float s_ez[KD], s_eZ[KD], s_inv[KD];
    __shared__ float s_red[8];

    for (int i = tid; i < KD; i += 256) {
        s_ez[i] = g_ez[(size_t)b * KD + i];
        s_eZ[i] = g_eZ[(size_t)b * KD + i];
        s_inv[i] = g_inv[(size_t)b * KD + i];
    }
    __syncthreads();

    const int j = tid & 63;          // constant per thread
    float ezj[PD], eZj[PD], invj[PD];
#pragma unroll
    for (int d = 0; d < PD; d++) {
        ezj[d] = s_ez[j * PD + d];
        eZj[d] = s_eZ[j * PD + d];
        invj[d] = s_inv[j * PD + d];
    }

    float relsum = 0.f;
    float* outc = out_cond + (size_t)b * (PK * PK);
    const float CLO = 1e-6f;
    const float CHI = 1.0f - 1e-6f;

#pragma unroll 2
    for (int q = 0; q < 16; q++) {
        int i = q * 4 + (tid >> 6);   // uniform within warp
        float prod = 1.f;
#pragma unroll
        for (int d = 0; d < PD; d++) {
            float S = s_ez[i * PD + d] + ezj[d];
            float T = s_eZ[i * PD + d] + eZj[d];
            float m = __log2f(S * T);          // log2(S*T); inf -> handled below
            float e = exp2f(-0.2f * m);        // (S*T)^{-1/5} = exp(2u)
            float w = 1.f + e;
            float lg = __logf(w);
            float small = e * (1.f - 0.5f * e);      // log1p(e) for tiny e
            float sp = (e > 0.015625f) ? lg : small; // = softplus(2u) = 2*side_int
            prod *= sp * invj[d];                    // ratio <= 1 per dim
        }
        float cond = fminf(fmaxf(prod, CLO), CHI);
        outc[i * PK + j] = cond;
        relsum += cond * Wrel[i * PK + j];
    }

    // block reduction of relsum (8 warps)
#pragma unroll
    for (int off = 16; off; off >>= 1) relsum += __shfl_down_sync(0xffffffffu, relsum, off);
    if ((tid & 31) == 0) s_red[tid >> 5] = relsum;
    __syncthreads();
    if (tid == 0) {
        float tot = 0.f;
#pragma unroll
        for (int w = 0; w < 8; w++) tot += s_red[w];
        tot += g_boxdot[b] + bbox[0] + brel[0];
        out_task[b] = 1.f / (1.f + expf(-tot));
    }
}

// ---------------- launch ----------------
extern "C" void kernel_launch(void* const* d_in, const int* in_sizes, int n_in,
                              void* d_out, int out_size) {
    const float* features = (const float*)d_in[0];  // (B,F)
    const float* Wp       = (const float*)d_in[1];  // (K,F,2D)
    const float* bp       = (const float*)d_in[2];  // (K,2D) flat = n index
    const float* Wprob    = (const float*)d_in[3];  // (K,2D)
    const float* bprob    = (const float*)d_in[4];  // (K,)
    const float* Wbox     = (const float*)d_in[5];  // (K*2D,1)
    const float* bbox     = (const float*)d_in[6];  // (1,)
    const float* Wrel     = (const float*)d_in[7];  // (K*K,1)
    const float* brel     = (const float*)d_in[8];  // (1,)

    float* out = (float*)d_out;
    float* out_task = out;                      // [B]
    float* out_cp   = out + PB;                 // [B,K]
    float* out_cond = out + PB + PB * PK;       // [B,K,K]

    // 0. transpose weights
    transpose_wp<<<(PF * PN + 255) / 256, 256>>>(Wp);

    // 1. GEMM: theta = features @ W + bp
    dim3 ggrid(PN / 128, PB / 128);   // (8, 32)
    sgemm_kernel<<<ggrid, 256>>>(features, bp);

    // 2. per (b,k) prep
    prep_kernel<<<PB, PK>>>(Wprob, bprob, Wbox, out_cp);

    // 3. pairwise cond + task logit
    pairwise_kernel<<<PB, 256>>>(Wrel, bbox, brel, out_task, out_cond);
}

// round 2
// speedup vs baseline: 1.8800x; 1.8800x over previous
#include <cuda_runtime.h>
#include <cuda_bf16.h>
#include <math.h>
#include <stdint.h>

// Problem constants
#define PB 4096     // batch
#define PF 2048     // features
#define PK 64       // concepts
#define PD 8        // box dim
#define PN 1024     // K*2D
#define KD 512      // K*D

// GEMM tiling
#define BM 128
#define BN 128
#define BK 32
#define APAD 8
#define BPAD 8
#define NK (PF / BK)   // 64

// ---------------- scratch (__device__ globals) ----------------
__device__ __nv_bfloat16 g_Ahi[PB * PF];
__device__ __nv_bfloat16 g_Alo[PB * PF];
__device__ __nv_bfloat16 g_Whi[PF * PN];
__device__ __nv_bfloat16 g_Wlo[PF * PN];
__device__ float g_theta[PB * PN];    // GEMM output
__device__ float g_ez[PB * KD];       // exp(+10 z)
__device__ float g_eZ[PB * KD];       // exp(-10 Z)
__device__ float g_inv[PB * KD];      // 1/softplus(2(Z-z))
__device__ float g_boxdot[PB];        // per-b flat_boxes @ Wbox partial

// ---------------- PTX helpers ----------------
__device__ __forceinline__ void cpasync16(void* dst, const void* src) {
    uint32_t d = (uint32_t)__cvta_generic_to_shared(dst);
    asm volatile("cp.async.cg.shared.global [%0], [%1], 16;\n" :: "r"(d), "l"(src));
}
__device__ __forceinline__ void ldsm_x4(uint32_t* r, uint32_t addr) {
    asm volatile("ldmatrix.sync.aligned.m8n8.x4.shared.b16 {%0,%1,%2,%3}, [%4];\n"
                 : "=r"(r[0]), "=r"(r[1]), "=r"(r[2]), "=r"(r[3]) : "r"(addr));
}
__device__ __forceinline__ void ldsm_x2t(uint32_t* r, uint32_t addr) {
    asm volatile("ldmatrix.sync.aligned.m8n8.x2.trans.shared.b16 {%0,%1}, [%2];\n"
                 : "=r"(r[0]), "=r"(r[1]) : "r"(addr));
}
__device__ __forceinline__ void mma16816(float* c, const uint32_t* a, const uint32_t* b) {
    asm volatile(
        "mma.sync.aligned.m16n8k16.row.col.f32.bf16.bf16.f32 "
        "{%0,%1,%2,%3}, {%4,%5,%6,%7}, {%8,%9}, {%0,%1,%2,%3};\n"
        : "+f"(c[0]), "+f"(c[1]), "+f"(c[2]), "+f"(c[3])
        : "r"(a[0]), "r"(a[1]), "r"(a[2]), "r"(a[3]), "r"(b[0]), "r"(b[1]));
}

// ---------------- kernel: convert A (features) to bf16 hi/lo ----------------
__global__ void cvtA_kernel(const float* __restrict__ A) {
    int i = (blockIdx.x * 256 + threadIdx.x) * 4;
    float4 v = *(const float4*)(A + i);
    __nv_bfloat16 hx = __float2bfloat16(v.x);
    __nv_bfloat16 hy = __float2bfloat16(v.y);
    __nv_bfloat16 hz = __float2bfloat16(v.z);
    __nv_bfloat16 hw = __float2bfloat16(v.w);
    __nv_bfloat162 h01; h01.x = hx; h01.y = hy;
    __nv_bfloat162 h23; h23.x = hz; h23.y = hw;
    *(__nv_bfloat162*)(g_Ahi + i)     = h01;
    *(__nv_bfloat162*)(g_Ahi + i + 2) = h23;
    __nv_bfloat162 l01, l23;
    l01.x = __float2bfloat16(v.x - __bfloat162float(hx));
    l01.y = __float2bfloat16(v.y - __bfloat162float(hy));
    l23.x = __float2bfloat16(v.z - __bfloat162float(hz));
    l23.y = __float2bfloat16(v.w - __bfloat162float(hw));
    *(__nv_bfloat162*)(g_Alo + i)     = l01;
    *(__nv_bfloat162*)(g_Alo + i + 2) = l23;
}

// ---------------- kernel: transpose + split Wp (K,F,2D) -> W[f][n] hi/lo ----------------
__global__ void cvtW_kernel(const float* __restrict__ Wp) {
    int idx = blockIdx.x * 256 + threadIdx.x;   // idx = f*1024 + n
    if (idx < PF * PN) {
        int f = idx >> 10;
        int n = idx & 1023;
        float v = Wp[(n >> 4) * (PF * 16) + f * 16 + (n & 15)];
        __nv_bfloat16 h = __float2bfloat16(v);
        g_Whi[idx] = h;
        g_Wlo[idx] = __float2bfloat16(v - __bfloat162float(h));
    }
}

// ---------------- kernel: bf16x3 tensor-core GEMM ----------------
struct SmemT {
    __nv_bfloat16 Ahi[2][BM][BK + APAD];
    __nv_bfloat16 Alo[2][BM][BK + APAD];
    __nv_bfloat16 Bhi[2][BK][BN + BPAD];
    __nv_bfloat16 Blo[2][BK][BN + BPAD];
};

__global__ __launch_bounds__(256) void gemm3_kernel(const float* __restrict__ bias) {
    extern __shared__ char sm_raw[];
    SmemT* sm = (SmemT*)sm_raw;
    const int tid = threadIdx.x;
    const int warp = tid >> 5;
    const int l = tid & 31;
    const int wm = warp >> 2;       // 0..1
    const int wn = warp & 3;        // 0..3
    const int row0 = blockIdx.y * BM;
    const int col0 = blockIdx.x * BN;

    float acc[4][4][4];
#pragma unroll
    for (int mi = 0; mi < 4; mi++)
#pragma unroll
        for (int ni = 0; ni < 4; ni++)
#pragma unroll
            for (int r = 0; r < 4; r++) acc[mi][ni][r] = 0.f;

    const __nv_bfloat16* Ah = g_Ahi + (size_t)row0 * PF;
    const __nv_bfloat16* Al = g_Alo + (size_t)row0 * PF;
    const __nv_bfloat16* Bh = g_Whi + col0;
    const __nv_bfloat16* Bl = g_Wlo + col0;

    const int arow = tid >> 2;          // 0..63
    const int acol = (tid & 3) * 8;     // 0,8,16,24
    const int brow = tid >> 4;          // 0..15
    const int bcol = (tid & 15) * 8;    // 0..120

    auto load_stage = [&](int kt, int s) {
        int k0 = kt * BK;
        const __nv_bfloat16* ah = Ah + k0;
        const __nv_bfloat16* al = Al + k0;
#pragma unroll
        for (int r = 0; r < 2; r++) {
            int row = arow + r * 64;
            cpasync16(&sm->Ahi[s][row][acol], ah + (size_t)row * PF + acol);
            cpasync16(&sm->Alo[s][row][acol], al + (size_t)row * PF + acol);
        }
        const __nv_bfloat16* bh = Bh + (size_t)k0 * PN;
        const __nv_bfloat16* bl = Bl + (size_t)k0 * PN;
#pragma unroll
        for (int r = 0; r < 2; r++) {
            int row = brow + r * 16;
            cpasync16(&sm->Bhi[s][row][bcol], bh + (size_t)row * PN + bcol);
            cpasync16(&sm->Blo[s][row][bcol], bl + (size_t)row * PN + bcol);
        }
        asm volatile("cp.async.commit_group;\n");
    };

    load_stage(0, 0);

    const int lr16 = l & 15;
    const int lhalf = (l >> 4) * 8;

    for (int kt = 0; kt < NK; kt++) {
        const int s = kt & 1;
        if (kt + 1 < NK) {
            load_stage(kt + 1, s ^ 1);
            asm volatile("cp.async.wait_group 1;\n");
        } else {
            asm volatile("cp.async.wait_group 0;\n");
        }
        __syncthreads();

#pragma unroll
        for (int ks = 0; ks < 2; ks++) {
            const int kk = ks * 16;
            uint32_t ah4[4][4], al4[4][4], bh2[4][2], bl2[4][2];
#pragma unroll
            for (int mi = 0; mi < 4; mi++) {
                int mrow = wm * 64 + mi * 16 + lr16;
                uint32_t addr = (uint32_t)__cvta_generic_to_shared(&sm->Ahi[s][mrow][kk + lhalf]);
                ldsm_x4(ah4[mi], addr);
                addr = (uint32_t)__cvta_generic_to_shared(&sm->Alo[s][mrow][kk + lhalf]);
                ldsm_x4(al4[mi], addr);
            }
#pragma unroll
            for (int ni = 0; ni < 4; ni++) {
                int nc = wn * 32 + ni * 8;
                uint32_t addr = (uint32_t)__cvta_generic_to_shared(&sm->Bhi[s][kk + lr16][nc]);
                ldsm_x2t(bh2[ni], addr);
                addr = (uint32_t)__cvta_generic_to_shared(&sm->Blo[s][kk + lr16][nc]);
                ldsm_x2t(bl2[ni], addr);
            }
#pragma unroll
            for (int mi = 0; mi < 4; mi++)
#pragma unroll
                for (int ni = 0; ni < 4; ni++) {
                    mma16816(acc[mi][ni], ah4[mi], bh2[ni]);
                    mma16816(acc[mi][ni], ah4[mi], bl2[ni]);
                    mma16816(acc[mi][ni], al4[mi], bh2[ni]);
                }
        }
        __syncthreads();
    }

    // epilogue: add bias, store fp32 theta
    const int rbase = row0 + wm * 64 + (l >> 2);
    const int cbase = col0 + wn * 32 + (l & 3) * 2;
#pragma unroll
    for (int mi = 0; mi < 4; mi++) {
#pragma unroll
        for (int ni = 0; ni < 4; ni++) {
            int r = rbase + mi * 16;
            int c = cbase + ni * 8;
            float b0 = bias[c], b1 = bias[c + 1];
            float2 v0; v0.x = acc[mi][ni][0] + b0; v0.y = acc[mi][ni][1] + b1;
            *(float2*)(g_theta + (size_t)r * PN + c) = v0;
            float2 v1; v1.x = acc[mi][ni][2] + b0; v1.y = acc[mi][ni][3] + b1;
            *(float2*)(g_theta + (size_t)(r + 8) * PN + c) = v1;
        }
    }
}

// accurate softplus
__device__ __forceinline__ float softplus_acc(float x) {
    float ax = fabsf(x);
    float r = log1pf(expf(-ax));
    return x > 0.f ? x + r : r;
}

// ---------------- kernel: per (b,k) prep ----------------
__global__ void prep_kernel(const float* __restrict__ Wprob,
                            const float* __restrict__ bprob,
                            const float* __restrict__ Wbox,
                            float* __restrict__ out_cp) {
    const int b = blockIdx.x;
    const int k = threadIdx.x;   // 64 threads
    const float* th = g_theta + (size_t)b * PN + k * 16;

    float z[PD], Z[PD], v[PD];
#pragma unroll
    for (int d = 0; d < PD; d++) z[d] = th[d];
#pragma unroll
    for (int d = 0; d < PD; d++) {
        v[d] = softplus_acc(th[8 + d]);   // Z - z
        Z[d] = z[d] + v[d];
    }

    const float* wp = Wprob + k * 16;
    float logit = bprob[k];
#pragma unroll
    for (int d = 0; d < PD; d++) logit += z[d] * wp[d] + Z[d] * wp[8 + d];
    float p = 1.f / (1.f + expf(-logit));
    out_cp[b * PK + k] = p;

    const float* wb = Wbox + k * 16;
    float bd = 0.f;
#pragma unroll
    for (int d = 0; d < PD; d++) bd += z[d] * wb[d] + Z[d] * wb[8 + d];
    bd *= p;

    const float C10 = 14.426950408889634f;  // 10/ln2
    float* ezp = g_ez + (size_t)b * KD + k * PD;
    float* eZp = g_eZ + (size_t)b * KD + k * PD;
    float* ivp = g_inv + (size_t)b * KD + k * PD;
#pragma unroll
    for (int d = 0; d < PD; d++) {
        ezp[d] = exp2f(z[d] * C10);
        eZp[d] = exp2f(-Z[d] * C10);
        float sp2 = 2.f * v[d] + log1pf(expf(-2.f * v[d]));  // softplus(2v), v>=0
        ivp[d] = 1.f / sp2;
    }

    __shared__ float red[64];
    red[k] = bd;
    __syncthreads();
    if (k < 32) {
        float s = red[k] + red[k + 32];
#pragma unroll
        for (int off = 16; off; off >>= 1) s += __shfl_down_sync(0xffffffffu, s, off);
        if (k == 0) g_boxdot[b] = s;
    }
}

// ---------------- kernel: pairwise cond + final task logit ----------------
__global__ __launch_bounds__(256) void pairwise_kernel(const float* __restrict__ Wrel,
                                                       const float* __restrict__ bbox,
                                                       const float* __restrict__ brel,
                                                       float* __restrict__ out_task,
                                                       float* __restrict__ out_cond) {
    const int b = blockIdx.x;
    const int tid = threadIdx.x;

    __shared__ float s_ez[KD], s_eZ[KD], s_inv[KD];
    __shared__ float s_red[8];

    for (int i = tid; i < KD; i += 256) {
        s_ez[i] = g_ez[(size_t)b * KD + i];
        s_eZ[i] = g_eZ[(size_t)b * KD + i];
        s_inv[i] = g_inv[(size_t)b * KD + i];
    }
    __syncthreads();

    const int j = tid & 63;
    float ezj[PD], eZj[PD], invj[PD];
#pragma unroll
    for (int d = 0; d < PD; d++) {
        ezj[d] = s_ez[j * PD + d];
        eZj[d] = s_eZ[j * PD + d];
        invj[d] = s_inv[j * PD + d];
    }

    float relsum = 0.f;
    float* outc = out_cond + (size_t)b * (PK * PK);
    const float CLO = 1e-6f;
    const float CHI = 1.0f - 1e-6f;

#pragma unroll 2
    for (int q = 0; q < 16; q++) {
        int i = q * 4 + (tid >> 6);   // uniform within warp
        float4 e0 = *(const float4*)(s_ez + i * PD);
        float4 e1 = *(const float4*)(s_ez + i * PD + 4);
        float4 f0 = *(const float4*)(s_eZ + i * PD);
        float4 f1 = *(const float4*)(s_eZ + i * PD + 4);
        float Si[PD] = {e0.x, e0.y, e0.z, e0.w, e1.x, e1.y, e1.z, e1.w};
        float Ti[PD] = {f0.x, f0.y, f0.z, f0.w, f1.x, f1.y, f1.z, f1.w};
        float prod = 1.f;
#pragma unroll
        for (int d = 0; d < PD; d++) {
            float S = Si[d] + ezj[d];
            float T = Ti[d] + eZj[d];
            float m = __log2f(S * T);
            float e = exp2f(-0.2f * m);        // (S*T)^{-1/5} = exp(2u)
            float sp = __logf(1.f + e);        // softplus(2u) = 2*side_int
            prod *= sp * invj[d];              // ratio <= 1 per dim
        }
        float cond = fminf(fmaxf(prod, CLO), CHI);
        outc[i * PK + j] = cond;
        relsum += cond * Wrel[i * PK + j];
    }

#pragma unroll
    for (int off = 16; off; off >>= 1) relsum += __shfl_down_sync(0xffffffffu, relsum, off);
    if ((tid & 31) == 0) s_red[tid >> 5] = relsum;
    __syncthreads();
    if (tid == 0) {
        float tot = 0.f;
#pragma unroll
        for (int w = 0; w < 8; w++) tot += s_red[w];
        tot += g_boxdot[b] + bbox[0] + brel[0];
        out_task[b] = 1.f / (1.f + expf(-tot));
    }
}

// ---------------- launch ----------------
extern "C" void kernel_launch(void* const* d_in, const int* in_sizes, int n_in,
                              void* d_out, int out_size) {
    const float* features = (const float*)d_in[0];  // (B,F)
    const float* Wp       = (const float*)d_in[1];  // (K,F,2D)
    const float* bp       = (const float*)d_in[2];  // (K,2D)
    const float* Wprob    = (const float*)d_in[3];  // (K,2D)
    const float* bprob    = (const float*)d_in[4];  // (K,)
    const float* Wbox     = (const float*)d_in[5];  // (K*2D,1)
    const float* bbox     = (const float*)d_in[6];  // (1,)
    const float* Wrel     = (const float*)d_in[7];  // (K*K,1)
    const float* brel     = (const float*)d_in[8];  // (1,)

    float* out = (float*)d_out;
    float* out_task = out;                      // [B]
    float* out_cp   = out + PB;                 // [B,K]
    float* out_cond = out + PB + PB * PK;       // [B,K,K]

    // 0. conversions
    cvtA_kernel<<<PB * PF / (256 * 4), 256>>>(features);
    cvtW_kernel<<<(PF * PN + 255) / 256, 256>>>(Wp);

    // 1. bf16x3 tensor-core GEMM
    int smem_bytes = (int)sizeof(SmemT);
    cudaFuncSetAttribute(gemm3_kernel, cudaFuncAttributeMaxDynamicSharedMemorySize, smem_bytes);
    dim3 ggrid(PN / BN, PB / BM);   // (8, 32)
    gemm3_kernel<<<ggrid, 256, smem_bytes>>>(bp);

    // 2. per (b,k) prep
    prep_kernel<<<PB, PK>>>(Wprob, bprob, Wbox, out_cp);

    // 3. pairwise cond + task logit
    pairwise_kernel<<<PB, 256>>>(Wrel, bbox, brel, out_task, out_cond);
}

// round 3
// speedup vs baseline: 2.2892x; 1.2177x over previous
#include <cuda_runtime.h>
#include <cuda_bf16.h>
#include <math.h>
#include <stdint.h>

// Problem constants
#define PB 4096     // batch
#define PF 2048     // features
#define PK 64       // concepts
#define PD 8        // box dim
#define PN 1024     // K*2D
#define KD 512      // K*D

// GEMM tiling
#define BM 128
#define BN 128
#define BK 32
#define APAD 8
#define BPAD 8
#define NK (PF / BK)   // 64

// ---------------- scratch (__device__ globals) ----------------
__device__ __nv_bfloat16 g_Ahi[PB * PF];
__device__ __nv_bfloat16 g_Alo[PB * PF];
__device__ __nv_bfloat16 g_Whi[PF * PN];
__device__ __nv_bfloat16 g_Wlo[PF * PN];
__device__ float g_theta[PB * PN];    // GEMM output
__device__ float g_ez[PB * KD];       // exp(+10 z)
__device__ float g_eZ[PB * KD];       // exp(-10 Z)
__device__ float g_vinv[PB * PK];     // prod_d 1/softplus(2(Z-z))
__device__ float g_boxdot[PB];        // per-b flat_boxes @ Wbox partial

// ---------------- PTX helpers ----------------
__device__ __forceinline__ void cpasync16(void* dst, const void* src) {
    uint32_t d = (uint32_t)__cvta_generic_to_shared(dst);
    asm volatile("cp.async.cg.shared.global [%0], [%1], 16;\n" :: "r"(d), "l"(src));
}
__device__ __forceinline__ void ldsm_x4(uint32_t* r, uint32_t addr) {
    asm volatile("ldmatrix.sync.aligned.m8n8.x4.shared.b16 {%0,%1,%2,%3}, [%4];\n"
                 : "=r"(r[0]), "=r"(r[1]), "=r"(r[2]), "=r"(r[3]) : "r"(addr));
}
__device__ __forceinline__ void ldsm_x2t(uint32_t* r, uint32_t addr) {
    asm volatile("ldmatrix.sync.aligned.m8n8.x2.trans.shared.b16 {%0,%1}, [%2];\n"
                 : "=r"(r[0]), "=r"(r[1]) : "r"(addr));
}
__device__ __forceinline__ void mma16816(float* c, const uint32_t* a, const uint32_t* b) {
    asm volatile(
        "mma.sync.aligned.m16n8k16.row.col.f32.bf16.bf16.f32 "
        "{%0,%1,%2,%3}, {%4,%5,%6,%7}, {%8,%9}, {%0,%1,%2,%3};\n"
        : "+f"(c[0]), "+f"(c[1]), "+f"(c[2]), "+f"(c[3])
        : "r"(a[0]), "r"(a[1]), "r"(a[2]), "r"(a[3]), "r"(b[0]), "r"(b[1]));
}
__device__ __forceinline__ float ex2_fast(float x) {
    float r;
    asm("ex2.approx.ftz.f32 %0, %1;" : "=f"(r) : "f"(x));
    return r;
}
__device__ __forceinline__ float lg2_fast(float x) {
    float r;
    asm("lg2.approx.ftz.f32 %0, %1;" : "=f"(r) : "f"(x));
    return r;
}

// ---------------- kernel: convert A (features) to bf16 hi/lo ----------------
__global__ void cvtA_kernel(const float* __restrict__ A) {
    int i = (blockIdx.x * 256 + threadIdx.x) * 4;
    float4 v = *(const float4*)(A + i);
    __nv_bfloat16 hx = __float2bfloat16(v.x);
    __nv_bfloat16 hy = __float2bfloat16(v.y);
    __nv_bfloat16 hz = __float2bfloat16(v.z);
    __nv_bfloat16 hw = __float2bfloat16(v.w);
    __nv_bfloat162 h01; h01.x = hx; h01.y = hy;
    __nv_bfloat162 h23; h23.x = hz; h23.y = hw;
    *(__nv_bfloat162*)(g_Ahi + i)     = h01;
    *(__nv_bfloat162*)(g_Ahi + i + 2) = h23;
    __nv_bfloat162 l01, l23;
    l01.x = __float2bfloat16(v.x - __bfloat162float(hx));
    l01.y = __float2bfloat16(v.y - __bfloat162float(hy));
    l23.x = __float2bfloat16(v.z - __bfloat162float(hz));
    l23.y = __float2bfloat16(v.w - __bfloat162float(hw));
    *(__nv_bfloat162*)(g_Alo + i)     = l01;
    *(__nv_bfloat162*)(g_Alo + i + 2) = l23;
}

// ---------------- kernel: transpose + split Wp (K,F,2D) -> W[f][n] hi/lo ----------------
__global__ void cvtW_kernel(const float* __restrict__ Wp) {
    int idx = blockIdx.x * 256 + threadIdx.x;   // idx = f*1024 + n
    if (idx < PF * PN) {
        int f = idx >> 10;
        int n = idx & 1023;
        float v = Wp[(n >> 4) * (PF * 16) + f * 16 + (n & 15)];
        __nv_bfloat16 h = __float2bfloat16(v);
        g_Whi[idx] = h;
        g_Wlo[idx] = __float2bfloat16(v - __bfloat162float(h));
    }
}

// ---------------- kernel: bf16x3 tensor-core GEMM ----------------
struct SmemT {
    __nv_bfloat16 Ahi[2][BM][BK + APAD];
    __nv_bfloat16 Alo[2][BM][BK + APAD];
    __nv_bfloat16 Bhi[2][BK][BN + BPAD];
    __nv_bfloat16 Blo[2][BK][BN + BPAD];
};

__global__ __launch_bounds__(256) void gemm3_kernel(const float* __restrict__ bias) {
    extern __shared__ char sm_raw[];
    SmemT* sm = (SmemT*)sm_raw;
    const int tid = threadIdx.x;
    const int warp = tid >> 5;
    const int l = tid & 31;
    const int wm = warp >> 2;       // 0..1
    const int wn = warp & 3;        // 0..3
    const int row0 = blockIdx.y * BM;
    const int col0 = blockIdx.x * BN;

    float acc[4][4][4];
#pragma unroll
    for (int mi = 0; mi < 4; mi++)
#pragma unroll
        for (int ni = 0; ni < 4; ni++)
#pragma unroll
            for (int r = 0; r < 4; r++) acc[mi][ni][r] = 0.f;

    const __nv_bfloat16* Ah = g_Ahi + (size_t)row0 * PF;
    const __nv_bfloat16* Al = g_Alo + (size_t)row0 * PF;
    const __nv_bfloat16* Bh = g_Whi + col0;
    const __nv_bfloat16* Bl = g_Wlo + col0;

    const int arow = tid >> 2;          // 0..63
    const int acol = (tid & 3) * 8;     // 0,8,16,24
    const int brow = tid >> 4;          // 0..15
    const int bcol = (tid & 15) * 8;    // 0..120

    auto load_stage = [&](int kt, int s) {
        int k0 = kt * BK;
        const __nv_bfloat16* ah = Ah + k0;
        const __nv_bfloat16* al = Al + k0;
#pragma unroll
        for (int r = 0; r < 2; r++) {
            int row = arow + r * 64;
            cpasync16(&sm->Ahi[s][row][acol], ah + (size_t)row * PF + acol);
            cpasync16(&sm->Alo[s][row][acol], al + (size_t)row * PF + acol);
        }
        const __nv_bfloat16* bh = Bh + (size_t)k0 * PN;
        const __nv_bfloat16* bl = Bl + (size_t)k0 * PN;
#pragma unroll
        for (int r = 0; r < 2; r++) {
            int row = brow + r * 16;
            cpasync16(&sm->Bhi[s][row][bcol], bh + (size_t)row * PN + bcol);
            cpasync16(&sm->Blo[s][row][bcol], bl + (size_t)row * PN + bcol);
        }
        asm volatile("cp.async.commit_group;\n");
    };

    load_stage(0, 0);

    const int lr16 = l & 15;
    const int lhalf = (l >> 4) * 8;

    for (int kt = 0; kt < NK; kt++) {
        const int s = kt & 1;
        if (kt + 1 < NK) {
            load_stage(kt + 1, s ^ 1);
            asm volatile("cp.async.wait_group 1;\n");
        } else {
            asm volatile("cp.async.wait_group 0;\n");
        }
        __syncthreads();

#pragma unroll
        for (int ks = 0; ks < 2; ks++) {
            const int kk = ks * 16;
            uint32_t ah4[4][4], al4[4][4], bh2[4][2], bl2[4][2];
#pragma unroll
            for (int mi = 0; mi < 4; mi++) {
                int mrow = wm * 64 + mi * 16 + lr16;
                uint32_t addr = (uint32_t)__cvta_generic_to_shared(&sm->Ahi[s][mrow][kk + lhalf]);
                ldsm_x4(ah4[mi], addr);
                addr = (uint32_t)__cvta_generic_to_shared(&sm->Alo[s][mrow][kk + lhalf]);
                ldsm_x4(al4[mi], addr);
            }
#pragma unroll
            for (int ni = 0; ni < 4; ni++) {
                int nc = wn * 32 + ni * 8;
                uint32_t addr = (uint32_t)__cvta_generic_to_shared(&sm->Bhi[s][kk + lr16][nc]);
                ldsm_x2t(bh2[ni], addr);
                addr = (uint32_t)__cvta_generic_to_shared(&sm->Blo[s][kk + lr16][nc]);
                ldsm_x2t(bl2[ni], addr);
            }
#pragma unroll
            for (int mi = 0; mi < 4; mi++)
#pragma unroll
                for (int ni = 0; ni < 4; ni++) {
                    mma16816(acc[mi][ni], ah4[mi], bh2[ni]);
                    mma16816(acc[mi][ni], ah4[mi], bl2[ni]);
                    mma16816(acc[mi][ni], al4[mi], bh2[ni]);
                }
        }
        __syncthreads();
    }

    // epilogue: add bias, store fp32 theta
    const int rbase = row0 + wm * 64 + (l >> 2);
    const int cbase = col0 + wn * 32 + (l & 3) * 2;
#pragma unroll
    for (int mi = 0; mi < 4; mi++) {
#pragma unroll
        for (int ni = 0; ni < 4; ni++) {
            int r = rbase + mi * 16;
            int c = cbase + ni * 8;
            float b0 = bias[c], b1 = bias[c + 1];
            float2 v0; v0.x = acc[mi][ni][0] + b0; v0.y = acc[mi][ni][1] + b1;
            *(float2*)(g_theta + (size_t)r * PN + c) = v0;
            float2 v1; v1.x = acc[mi][ni][2] + b0; v1.y = acc[mi][ni][3] + b1;
            *(float2*)(g_theta + (size_t)(r + 8) * PN + c) = v1;
        }
    }
}

// fast softplus: ln(1+e^x) with hardware MUFU (rel err ~1e-6, fine for 1e-3 gate)
__device__ __forceinline__ float softplus_f(float x) {
    float e = __expf(-fabsf(x));
    return fmaxf(x, 0.f) + __logf(1.f + e);
}

// ---------------- kernel: per (b,k) prep ----------------
// 256 threads = 4 batches x 64 concepts. Fully coalesced float4 I/O.
__global__ __launch_bounds__(256) void prep_kernel(const float* __restrict__ Wprob,
                                                   const float* __restrict__ bprob,
                                                   const float* __restrict__ Wbox,
                                                   float* __restrict__ out_cp) {
    const int tid = threadIdx.x;
    const int k = tid & 63;
    const int b = blockIdx.x * 4 + (tid >> 6);
    const float* th = g_theta + (size_t)b * PN + k * 16;

    float4 t0 = *(const float4*)(th);
    float4 t1 = *(const float4*)(th + 4);
    float4 t2 = *(const float4*)(th + 8);
    float4 t3 = *(const float4*)(th + 12);
    float z[PD] = {t0.x, t0.y, t0.z, t0.w, t1.x, t1.y, t1.z, t1.w};
    float w2[PD] = {t2.x, t2.y, t2.z, t2.w, t3.x, t3.y, t3.z, t3.w};

    float Z[PD], v[PD];
#pragma unroll
    for (int d = 0; d < PD; d++) {
        v[d] = softplus_f(w2[d]);    // Z - z >= 0
        Z[d] = z[d] + v[d];
    }

    // concept logit
    const float* wp = Wprob + k * 16;
    float logit = bprob[k];
#pragma unroll
    for (int d = 0; d < PD; d++) logit += z[d] * wp[d] + Z[d] * wp[8 + d];
    float p = 1.f / (1.f + __expf(-logit));
    out_cp[b * PK + k] = p;

    // box-dot partial: p * (z . Wbox[k][0:8] + Z . Wbox[k][8:16])
    const float* wb = Wbox + k * 16;
    float bd = 0.f;
#pragma unroll
    for (int d = 0; d < PD; d++) bd += z[d] * wb[d] + Z[d] * wb[8 + d];
    bd *= p;

    // exp tables + scalar inverse box volume factor
    const float C10 = 14.426950408889634f;  // 10/ln2
    float ez[PD], eZ[PD];
    float vprod = 1.f;
#pragma unroll
    for (int d = 0; d < PD; d++) {
        ez[d] = ex2_fast(z[d] * C10);
        eZ[d] = ex2_fast(-Z[d] * C10);
        float sp2 = 2.f * v[d] + __logf(1.f + __expf(-2.f * v[d]));  // softplus(2v)
        vprod *= sp2;
    }
    float* ezp = g_ez + (size_t)b * KD + k * PD;
    float* eZp = g_eZ + (size_t)b * KD + k * PD;
    *(float4*)(ezp)     = make_float4(ez[0], ez[1], ez[2], ez[3]);
    *(float4*)(ezp + 4) = make_float4(ez[4], ez[5], ez[6], ez[7]);
    *(float4*)(eZp)     = make_float4(eZ[0], eZ[1], eZ[2], eZ[3]);
    *(float4*)(eZp + 4) = make_float4(eZ[4], eZ[5], eZ[6], eZ[7]);
    g_vinv[b * PK + k] = 1.f / vprod;

    // reduce bd over each group of 64 threads (2 warps per b)
    float s = bd;
#pragma unroll
    for (int off = 16; off; off >>= 1) s += __shfl_down_sync(0xffffffffu, s, off);
    __shared__ float sred[8];
    if ((tid & 31) == 0) sred[tid >> 5] = s;
    __syncthreads();
    if (tid < 4) g_boxdot[blockIdx.x * 4 + tid] = sred[2 * tid] + sred[2 * tid + 1];
}

// ---------------- kernel: pairwise cond (symmetric half) + final task logit ----------------
__global__ __launch_bounds__(256) void pairwise_kernel(const float* __restrict__ Wrel,
                                                       const float* __restrict__ bbox,
                                                       const float* __restrict__ brel,
                                                       float* __restrict__ out_task,
                                                       float* __restrict__ out_cond) {
    const int b = blockIdx.x;
    const int tid = threadIdx.x;

    __shared__ float s_ez[KD], s_eZ[KD], s_vinv[PK];
    __shared__ float s_cond[PK * PK];
    __shared__ float s_red[8];

    if (tid < 128) {
        *(float4*)(s_ez + tid * 4) = *(const float4*)(g_ez + (size_t)b * KD + tid * 4);
        *(float4*)(s_eZ + tid * 4) = *(const float4*)(g_eZ + (size_t)b * KD + tid * 4);
    } else if (tid < 144) {
        int x = (tid - 128) * 4;
        *(float4*)(s_vinv + x) = *(const float4*)(g_vinv + (size_t)b * PK + x);
    }
    __syncthreads();

    // thread -> (i fixed, off strided). Covers all unordered pairs:
    // off in {g, g+4, ..., <=32}; g = tid>>6. off==32 pairs computed twice (benign).
    const int i = tid & 63;
    const int g = tid >> 6;
    float ezi[PD], eZi[PD];
#pragma unroll
    for (int d = 0; d < PD; d += 4) {
        float4 a = *(const float4*)(s_ez + i * PD + d);
        ezi[d] = a.x; ezi[d+1] = a.y; ezi[d+2] = a.z; ezi[d+3] = a.w;
        float4 c = *(const float4*)(s_eZ + i * PD + d);
        eZi[d] = c.x; eZi[d+1] = c.y; eZi[d+2] = c.z; eZi[d+3] = c.w;
    }
    const float vinv_i = s_vinv[i];

    const float CLO = 1e-6f;
    const float CHI = 1.0f - 1e-6f;
    const float LN2P8 = 0.05328484f;   // ln(2)^8

    const int qmax = (g == 0) ? 9 : 8;
    for (int q = 0; q < qmax; q++) {
        const int off = g + 4 * q;
        const int j = (i + off) & 63;
        float prod = LN2P8;
#pragma unroll
        for (int d = 0; d < PD; d++) {
            float S = ezi[d] + s_ez[j * PD + d];
            float T = eZi[d] + s_eZ[j * PD + d];
            float m = lg2_fast(S * T);
            float e = ex2_fast(-0.2f * m);     // (S*T)^{-1/5} = exp(2u)
            prod *= lg2_fast(1.f + e);         // log2-domain softplus(2u)
        }
        float ci = fminf(fmaxf(prod * s_vinv[j], CLO), CHI);  // cond(i,j)
        float cj = fminf(fmaxf(prod * vinv_i,   CLO), CHI);   // cond(j,i)
        s_cond[i * PK + j] = ci;
        s_cond[j * PK + i] = cj;
    }
    __syncthreads();

    // coalesced writeout + fused Wrel dot
    float relsum = 0.f;
    float* outp = out_cond + (size_t)b * (PK * PK);
#pragma unroll
    for (int r = 0; r < 4; r++) {
        int idx = (tid + r * 256) * 4;
        float4 c = *(const float4*)(s_cond + idx);
        float4 w = *(const float4*)(Wrel + idx);
        relsum += c.x * w.x + c.y * w.y + c.z * w.z + c.w * w.w;
        *(float4*)(outp + idx) = c;
    }

#pragma unroll
    for (int off = 16; off; off >>= 1) relsum += __shfl_down_sync(0xffffffffu, relsum, off);
    if ((tid & 31) == 0) s_red[tid >> 5] = relsum;
    __syncthreads();
    if (tid == 0) {
        float tot = 0.f;
#pragma unroll
        for (int w = 0; w < 8; w++) tot += s_red[w];
        tot += g_boxdot[b] + bbox[0] + brel[0];
        out_task[b] = 1.f / (1.f + __expf(-tot));
    }
}

// ---------------- launch ----------------
extern "C" void kernel_launch(void* const* d_in, const int* in_sizes, int n_in,
                              void* d_out, int out_size) {
    const float* features = (const float*)d_in[0];  // (B,F)
    const float* Wp       = (const float*)d_in[1];  // (K,F,2D)
    const float* bp       = (const float*)d_in[2];  // (K,2D)
    const float* Wprob    = (const float*)d_in[3];  // (K,2D)
    const float* bprob    = (const float*)d_in[4];  // (K,)
    const float* Wbox     = (const float*)d_in[5];  // (K*2D,1)
    const float* bbox     = (const float*)d_in[6];  // (1,)
    const float* Wrel     = (const float*)d_in[7];  // (K*K,1)
    const float* brel     = (const float*)d_in[8];  // (1,)

    float* out = (float*)d_out;
    float* out_task = out;                      // [B]
    float* out_cp   = out + PB;                 // [B,K]
    float* out_cond = out + PB + PB * PK;       // [B,K,K]

    // 0. conversions
    cvtA_kernel<<<PB * PF / (256 * 4), 256>>>(features);
    cvtW_kernel<<<(PF * PN + 255) / 256, 256>>>(Wp);

    // 1. bf16x3 tensor-core GEMM
    int smem_bytes = (int)sizeof(SmemT);
    cudaFuncSetAttribute(gemm3_kernel, cudaFuncAttributeMaxDynamicSharedMemorySize, smem_bytes);
    dim3 ggrid(PN / BN, PB / BM);   // (8, 32)
    gemm3_kernel<<<ggrid, 256, smem_bytes>>>(bp);

    // 2. per (b,k) prep
    prep_kernel<<<PB / 4, 256>>>(Wprob, bprob, Wbox, out_cp);

    // 3. pairwise cond + task logit
    pairwise_kernel<<<PB, 256>>>(Wrel, bbox, brel, out_task, out_cond);
}